// round 3
// baseline (speedup 1.0000x reference)
#include <cuda_runtime.h>
#include <cuda_fp16.h>

#define FEAT 4096
#define TT   2048
#define ODIM 512
#define NCTA 148
#define NTHREADS 1024
#define SMEMB (28 * FEAT * 2)   // 28 rows of fp16 weights = 229376 bytes

// Static device scratch (no runtime allocation allowed)
__device__ __half   d_Wh[(size_t)FEAT * FEAT];      // fp16 W_res, 33.5 MB
__device__ __half   d_G[(size_t)(TT + 1) * FEAT];   // feats history (fp16), 16.8 MB
__device__ unsigned d_flag[256];                    // per-CTA step flags

// ---------------------------------------------------------------------------
// fp32 -> fp16 weight conversion
// ---------------------------------------------------------------------------
__global__ void convert_kernel(const float* __restrict__ W) {
    size_t n = (size_t)FEAT * FEAT / 4;
    for (size_t i = blockIdx.x * (size_t)blockDim.x + threadIdx.x; i < n;
         i += (size_t)gridDim.x * blockDim.x) {
        float4 v = reinterpret_cast<const float4*>(W)[i];
        __half2 h0 = __floats2half2_rn(v.x, v.y);
        __half2 h1 = __floats2half2_rn(v.z, v.w);
        uint2 u;
        u.x = *reinterpret_cast<unsigned*>(&h0);
        u.y = *reinterpret_cast<unsigned*>(&h1);
        reinterpret_cast<uint2*>(d_Wh)[i] = u;
    }
}

// ---------------------------------------------------------------------------
// Sync primitives
// ---------------------------------------------------------------------------
__device__ __forceinline__ unsigned ld_acq(const unsigned* p) {
    unsigned v;
    asm volatile("ld.acquire.gpu.global.u32 %0, [%1];" : "=r"(v) : "l"(p) : "memory");
    return v;
}
__device__ __forceinline__ void st_rel(unsigned* p, unsigned v) {
    asm volatile("st.release.gpu.global.u32 [%0], %1;" :: "l"(p), "r"(v) : "memory");
}

__device__ __forceinline__ void h8_to_f(uint4 u, float* o) {
    __half2* h = reinterpret_cast<__half2*>(&u);
    float2 a = __half22float2(h[0]);
    float2 b = __half22float2(h[1]);
    float2 c = __half22float2(h[2]);
    float2 d = __half22float2(h[3]);
    o[0] = a.x; o[1] = a.y; o[2] = b.x; o[3] = b.y;
    o[4] = c.x; o[5] = c.y; o[6] = d.x; o[7] = d.y;
}

// ---------------------------------------------------------------------------
// Persistent recurrence kernel: 148 CTAs, each owns <=28 rows of W in SMEM.
// Sync: per-CTA release flags (no atomics, no same-address contention).
// Warp layout: 32 warps = 4 row-groups x 8 k-groups.
//   warp w: rg = w&3 (rows rg*7..rg*7+6), kg = w>>2 (k in [kg*512, kg*512+512))
//   lane l: 2 chunks of 8 contiguous halves at cb = kg*512 + l*8 and cb+256
// ---------------------------------------------------------------------------
extern "C" __global__ void __launch_bounds__(NTHREADS, 1)
rc_kernel(const float* __restrict__ x) {
    extern __shared__ __half sW[];            // [nrows][FEAT]
    __shared__ float sPart[28][8];

    const int b   = blockIdx.x;
    const int tid = threadIdx.x;

    // Row distribution: first 100 CTAs get 28 rows, last 48 get 27 (=4096).
    int r0, nrows;
    if (b < 100) { r0 = b * 28;               nrows = 28; }
    else         { r0 = 2800 + (b - 100) * 27; nrows = 27; }

    // Stage W slice into SMEM (once)
    {
        const uint4* wg = reinterpret_cast<const uint4*>(d_Wh + (size_t)r0 * FEAT);
        uint4* ws = reinterpret_cast<uint4*>(sW);
        int nv = nrows * FEAT / 8;            // uint4 = 8 halfs
        for (int i = tid; i < nv; i += NTHREADS) ws[i] = wg[i];
    }
    __syncthreads();

    const int w    = tid >> 5;
    const int lane = tid & 31;
    const int rg   = w & 3;
    const int kg   = w >> 2;
    const int rbeg = rg * 7;
    const int rend = min(rbeg + 7, nrows);
    const int cb   = kg * 512 + lane * 8;

    for (int t = 0; t < TT; ++t) {
        // Prefetch x[:, t] for this CTA's rows (independent of the barrier)
        float xv = 0.f;
        if (tid < nrows) xv = __ldg(&x[(size_t)(r0 + tid) * TT + t]);

        if (t > 0) {
            if (tid < NCTA) {
                while (ld_acq(&d_flag[tid]) < (unsigned)t) { }
            }
            __syncthreads();
        }

        // Load this lane's 16 features (fp16 -> fp32 once, reused for 7 rows)
        const __half* f = d_G + (size_t)t * FEAT;
        uint4 fa = __ldcg(reinterpret_cast<const uint4*>(f + cb));
        uint4 fb = __ldcg(reinterpret_cast<const uint4*>(f + cb + 256));
        float fr[16];
        h8_to_f(fa, fr);
        h8_to_f(fb, fr + 8);

        float acc[7];
        #pragma unroll
        for (int j = 0; j < 7; ++j) acc[j] = 0.f;

        #pragma unroll
        for (int j = 0; j < 7; ++j) {
            int r = rbeg + j;
            if (r < rend) {
                const __half* wr = sW + (size_t)r * FEAT + cb;
                uint4 wa = *reinterpret_cast<const uint4*>(wr);
                uint4 wb = *reinterpret_cast<const uint4*>(wr + 256);
                float wf[16];
                h8_to_f(wa, wf);
                h8_to_f(wb, wf + 8);
                float s = 0.f;
                #pragma unroll
                for (int q = 0; q < 16; ++q) s = fmaf(wf[q], fr[q], s);
                acc[j] = s;
            }
        }

        // Warp reduction over 32 lanes for each of this warp's rows
        #pragma unroll
        for (int j = 0; j < 7; ++j) {
            float v = acc[j];
            v += __shfl_down_sync(0xFFFFFFFFu, v, 16);
            v += __shfl_down_sync(0xFFFFFFFFu, v, 8);
            v += __shfl_down_sync(0xFFFFFFFFu, v, 4);
            v += __shfl_down_sync(0xFFFFFFFFu, v, 2);
            v += __shfl_down_sync(0xFFFFFFFFu, v, 1);
            if (lane == 0 && rbeg + j < rend) sPart[rbeg + j][kg] = v;
        }
        __syncthreads();

        // Warp 0 finishes: sum partials, clamp, store slice, release flag
        if (w == 0) {
            if (lane < nrows) {
                float s = 0.f;
                #pragma unroll
                for (int k = 0; k < 8; ++k) s += sPart[lane][k];
                s += xv;
                s = fminf(fmaxf(s, -1.f), 1.f);
                d_G[(size_t)(t + 1) * FEAT + r0 + lane] = __float2half_rn(s);
            }
            __syncwarp();
            if (lane == 0) st_rel(&d_flag[b], (unsigned)(t + 1));
        }
        // No extra syncthreads here: the next iteration's post-poll
        // __syncthreads (which warp 0 reaches only after the flag store)
        // orders sPart reuse; pollers wait on their producers' flags.
    }
}

// ---------------------------------------------------------------------------
// Readout GEMM: out[o][t] = sum_f w_out[o][f] * G[t+1][f]   (G is fp16)
// 64x64 tile per block, BK=32, 256 threads, 4x4 micro-tile per thread.
// ---------------------------------------------------------------------------
__global__ void __launch_bounds__(256)
out_gemm(const float* __restrict__ wout, float* __restrict__ out) {
    __shared__ float As[32][65];   // As[k][i]  (i: out rows)
    __shared__ float Bs[32][65];   // Bs[k][j]  (j: timesteps)

    const int t0 = blockIdx.x * 64;
    const int o0 = blockIdx.y * 64;
    const int tid = threadIdx.x;
    const int tx = tid & 15, ty = tid >> 4;

    float c[4][4];
    #pragma unroll
    for (int p = 0; p < 4; ++p)
        #pragma unroll
        for (int q = 0; q < 4; ++q) c[p][q] = 0.f;

    for (int k0 = 0; k0 < FEAT; k0 += 32) {
        // load A tile: 64x32 fp32 (2048 floats -> 2x 256 threads x float4)
        #pragma unroll
        for (int it = 0; it < 2; ++it) {
            int idx = it * 256 + tid;          // 0..511
            int i  = idx >> 3;                 // 0..63
            int kv = (idx & 7) * 4;            // 0,4,..28
            float4 v = *reinterpret_cast<const float4*>(
                &wout[(size_t)(o0 + i) * FEAT + k0 + kv]);
            As[kv + 0][i] = v.x; As[kv + 1][i] = v.y;
            As[kv + 2][i] = v.z; As[kv + 3][i] = v.w;
        }
        // load B tile (fp16 G): 64 timesteps x 32 k; 256 threads x 8 halves
        {
            int j  = tid >> 2;                 // 0..63
            int kv = (tid & 3) * 8;            // 0,8,16,24
            uint4 u = *reinterpret_cast<const uint4*>(
                &d_G[(size_t)(t0 + j + 1) * FEAT + k0 + kv]);
            float bf[8];
            h8_to_f(u, bf);
            #pragma unroll
            for (int q = 0; q < 8; ++q) Bs[kv + q][j] = bf[q];
        }
        __syncthreads();

        #pragma unroll
        for (int kk = 0; kk < 32; ++kk) {
            float a[4], bb[4];
            #pragma unroll
            for (int p = 0; p < 4; ++p) a[p] = As[kk][ty * 4 + p];
            #pragma unroll
            for (int q = 0; q < 4; ++q) bb[q] = Bs[kk][tx * 4 + q];
            #pragma unroll
            for (int p = 0; p < 4; ++p)
                #pragma unroll
                for (int q = 0; q < 4; ++q)
                    c[p][q] = fmaf(a[p], bb[q], c[p][q]);
        }
        __syncthreads();
    }

    #pragma unroll
    for (int p = 0; p < 4; ++p)
        #pragma unroll
        for (int q = 0; q < 4; ++q)
            out[(size_t)(o0 + ty * 4 + p) * TT + t0 + tx * 4 + q] = c[p][q];
}

// ---------------------------------------------------------------------------
extern "C" void kernel_launch(void* const* d_in, const int* in_sizes, int n_in,
                              void* d_out, int out_size) {
    const float* x    = (const float*)d_in[0];   // [4096, 2048]
    const float* Wres = (const float*)d_in[1];   // [4096, 4096]
    const float* wout = (const float*)d_in[2];   // [512, 4096]
    float* out = (float*)d_out;                  // [512, 2048]

    cudaFuncSetAttribute(rc_kernel, cudaFuncAttributeMaxDynamicSharedMemorySize, SMEMB);

    void* flagp = nullptr;
    void* gp    = nullptr;
    cudaGetSymbolAddress(&flagp, d_flag);
    cudaGetSymbolAddress(&gp, d_G);
    cudaMemsetAsync(flagp, 0, 256 * sizeof(unsigned));   // reset step flags
    cudaMemsetAsync(gp, 0, FEAT * sizeof(__half));       // feats_0 = 0 (fp16 zeros)

    convert_kernel<<<1024, 256>>>(Wres);
    rc_kernel<<<NCTA, NTHREADS, SMEMB>>>(x);
    out_gemm<<<dim3(TT / 64, ODIM / 64), 256>>>(wout, out);
}

// round 4
// speedup vs baseline: 1.2547x; 1.2547x over previous
#include <cuda_runtime.h>
#include <cuda_fp16.h>

#define FEAT 4096
#define TT   2048
#define ODIM 512
#define NCTA 148
#define NTHREADS 1024
#define SMEMB (28 * FEAT * 2)   // 28 rows of fp16 weights = 229376 bytes

// Static device scratch (no runtime allocation allowed)
__device__ __half   d_Wh[(size_t)FEAT * FEAT];      // fp16 W_res, 33.5 MB
__device__ __half   d_G[(size_t)(TT + 1) * FEAT];   // feats history (fp16), 16.8 MB
__device__ unsigned d_flag[256];                    // per-CTA step flags (padded)

// ---------------------------------------------------------------------------
// fp32 -> fp16 weight conversion
// ---------------------------------------------------------------------------
__global__ void convert_kernel(const float* __restrict__ W) {
    size_t n = (size_t)FEAT * FEAT / 4;
    for (size_t i = blockIdx.x * (size_t)blockDim.x + threadIdx.x; i < n;
         i += (size_t)gridDim.x * blockDim.x) {
        float4 v = reinterpret_cast<const float4*>(W)[i];
        __half2 h0 = __floats2half2_rn(v.x, v.y);
        __half2 h1 = __floats2half2_rn(v.z, v.w);
        uint2 u;
        u.x = *reinterpret_cast<unsigned*>(&h0);
        u.y = *reinterpret_cast<unsigned*>(&h1);
        reinterpret_cast<uint2*>(d_Wh)[i] = u;
    }
}

// ---------------------------------------------------------------------------
// Sync primitives
// ---------------------------------------------------------------------------
__device__ __forceinline__ void st_rel(unsigned* p, unsigned v) {
    asm volatile("st.release.gpu.global.u32 [%0], %1;" :: "l"(p), "r"(v) : "memory");
}
__device__ __forceinline__ uint4 ld_vol4(const uint4* p) {
    uint4 v;
    asm volatile("ld.volatile.global.v4.u32 {%0,%1,%2,%3}, [%4];"
                 : "=r"(v.x), "=r"(v.y), "=r"(v.z), "=r"(v.w) : "l"(p) : "memory");
    return v;
}
__device__ __forceinline__ void fence_acq() {
    asm volatile("fence.acq_rel.gpu;" ::: "memory");
}

__device__ __forceinline__ void h8_to_f(uint4 u, float* o) {
    __half2* h = reinterpret_cast<__half2*>(&u);
    float2 a = __half22float2(h[0]);
    float2 b = __half22float2(h[1]);
    float2 c = __half22float2(h[2]);
    float2 d = __half22float2(h[3]);
    o[0] = a.x; o[1] = a.y; o[2] = b.x; o[3] = b.y;
    o[4] = c.x; o[5] = c.y; o[6] = d.x; o[7] = d.y;
}

// ---------------------------------------------------------------------------
// Persistent recurrence kernel: 148 CTAs, each owns <=28 rows of W in SMEM.
// Sync: per-CTA release flags; ONE vectorized polling warp per CTA.
// Warp layout: 32 warps = 4 row-groups x 8 k-groups.
//   warp w: rg = w&3 (rows rg*7..rg*7+6), kg = w>>2 (k in [kg*512, kg*512+512))
//   lane l: 2 chunks of 8 contiguous halves at cb = kg*512 + l*8 and cb+256
// ---------------------------------------------------------------------------
extern "C" __global__ void __launch_bounds__(NTHREADS, 1)
rc_kernel(const float* __restrict__ x) {
    extern __shared__ __half sW[];            // [nrows][FEAT]
    __shared__ float sPart[28][9];            // padded: stride 9 -> conflict-free

    const int b   = blockIdx.x;
    const int tid = threadIdx.x;

    // Row distribution: first 100 CTAs get 28 rows, last 48 get 27 (=4096).
    int r0, nrows;
    if (b < 100) { r0 = b * 28;               nrows = 28; }
    else         { r0 = 2800 + (b - 100) * 27; nrows = 27; }

    // Stage W slice into SMEM (once)
    {
        const uint4* wg = reinterpret_cast<const uint4*>(d_Wh + (size_t)r0 * FEAT);
        uint4* ws = reinterpret_cast<uint4*>(sW);
        int nv = nrows * FEAT / 8;            // uint4 = 8 halfs
        for (int i = tid; i < nv; i += NTHREADS) ws[i] = wg[i];
    }
    __syncthreads();

    const int w    = tid >> 5;
    const int lane = tid & 31;
    const int rg   = w & 3;
    const int kg   = w >> 2;
    const int rbeg = rg * 7;
    const int rend = min(rbeg + 7, nrows);
    const int cb   = kg * 512 + lane * 8;
    const uint4* flag4 = reinterpret_cast<const uint4*>(d_flag);

    for (int t = 0; t < TT; ++t) {
        // Prefetch x[:, t] for this CTA's rows (in flight during the poll)
        float xv = 0.f;
        if (w == 0 && lane < nrows) xv = __ldg(&x[(size_t)(r0 + lane) * TT + t]);

        if (t > 0) {
            if (w == 0) {
                // Warp 0 polls all 256 (padded) flags: 2 x v4 loads per lane.
                const unsigned tu = (unsigned)t;
                for (;;) {
                    uint4 a = ld_vol4(flag4 + lane);
                    uint4 c = ld_vol4(flag4 + 32 + lane);
                    unsigned m = min(min(a.x, a.y), min(a.z, a.w));
                    unsigned m2 = min(min(c.x, c.y), min(c.z, c.w));
                    if (__all_sync(0xFFFFFFFFu, min(m, m2) >= tu)) break;
                }
                fence_acq();
            }
            __syncthreads();
        }

        // Load this lane's 16 features (fp16 -> fp32 once, reused for 7 rows)
        const __half* f = d_G + (size_t)t * FEAT;
        uint4 fa = __ldcg(reinterpret_cast<const uint4*>(f + cb));
        uint4 fb = __ldcg(reinterpret_cast<const uint4*>(f + cb + 256));
        float fr[16];
        h8_to_f(fa, fr);
        h8_to_f(fb, fr + 8);

        float acc[7];
        #pragma unroll
        for (int j = 0; j < 7; ++j) acc[j] = 0.f;

        #pragma unroll
        for (int j = 0; j < 7; ++j) {
            int r = rbeg + j;
            if (r < rend) {
                const __half* wr = sW + (size_t)r * FEAT + cb;
                uint4 wa = *reinterpret_cast<const uint4*>(wr);
                uint4 wb = *reinterpret_cast<const uint4*>(wr + 256);
                float wf[16];
                h8_to_f(wa, wf);
                h8_to_f(wb, wf + 8);
                float s = 0.f;
                #pragma unroll
                for (int q = 0; q < 16; ++q) s = fmaf(wf[q], fr[q], s);
                acc[j] = s;
            }
        }

        // Warp reduction over 32 lanes for each of this warp's rows
        #pragma unroll
        for (int j = 0; j < 7; ++j) {
            float v = acc[j];
            v += __shfl_down_sync(0xFFFFFFFFu, v, 16);
            v += __shfl_down_sync(0xFFFFFFFFu, v, 8);
            v += __shfl_down_sync(0xFFFFFFFFu, v, 4);
            v += __shfl_down_sync(0xFFFFFFFFu, v, 2);
            v += __shfl_down_sync(0xFFFFFFFFu, v, 1);
            if (lane == 0 && rbeg + j < rend) sPart[rbeg + j][kg] = v;
        }
        __syncthreads();

        // Warp 0 finishes: sum partials, clamp, store slice, release flag.
        // All released data is produced by warp 0 itself -> syncwarp suffices
        // before the cumulative release store.
        if (w == 0) {
            if (lane < nrows) {
                float s = 0.f;
                #pragma unroll
                for (int k = 0; k < 8; ++k) s += sPart[lane][k];
                s += xv;
                s = fminf(fmaxf(s, -1.f), 1.f);
                d_G[(size_t)(t + 1) * FEAT + r0 + lane] = __float2half_rn(s);
            }
            __syncwarp();
            if (lane == 0) st_rel(&d_flag[b], (unsigned)(t + 1));
        }
        __syncthreads();   // protects sPart for the next iteration
    }
}

// ---------------------------------------------------------------------------
// Readout GEMM: out[o][t] = sum_f w_out[o][f] * G[t+1][f]   (G is fp16)
// 64x64 tile per block, BK=32, 256 threads, 4x4 micro-tile per thread.
// ---------------------------------------------------------------------------
__global__ void __launch_bounds__(256)
out_gemm(const float* __restrict__ wout, float* __restrict__ out) {
    __shared__ float As[32][65];   // As[k][i]  (i: out rows)
    __shared__ float Bs[32][65];   // Bs[k][j]  (j: timesteps)

    const int t0 = blockIdx.x * 64;
    const int o0 = blockIdx.y * 64;
    const int tid = threadIdx.x;
    const int tx = tid & 15, ty = tid >> 4;

    float c[4][4];
    #pragma unroll
    for (int p = 0; p < 4; ++p)
        #pragma unroll
        for (int q = 0; q < 4; ++q) c[p][q] = 0.f;

    for (int k0 = 0; k0 < FEAT; k0 += 32) {
        // load A tile: 64x32 fp32 (2048 floats -> 2x 256 threads x float4)
        #pragma unroll
        for (int it = 0; it < 2; ++it) {
            int idx = it * 256 + tid;          // 0..511
            int i  = idx >> 3;                 // 0..63
            int kv = (idx & 7) * 4;            // 0,4,..28
            float4 v = *reinterpret_cast<const float4*>(
                &wout[(size_t)(o0 + i) * FEAT + k0 + kv]);
            As[kv + 0][i] = v.x; As[kv + 1][i] = v.y;
            As[kv + 2][i] = v.z; As[kv + 3][i] = v.w;
        }
        // load B tile (fp16 G): 64 timesteps x 32 k; 256 threads x 8 halves
        {
            int j  = tid >> 2;                 // 0..63
            int kv = (tid & 3) * 8;            // 0,8,16,24
            uint4 u = *reinterpret_cast<const uint4*>(
                &d_G[(size_t)(t0 + j + 1) * FEAT + k0 + kv]);
            float bf[8];
            h8_to_f(u, bf);
            #pragma unroll
            for (int q = 0; q < 8; ++q) Bs[kv + q][j] = bf[q];
        }
        __syncthreads();

        #pragma unroll
        for (int kk = 0; kk < 32; ++kk) {
            float a[4], bb[4];
            #pragma unroll
            for (int p = 0; p < 4; ++p) a[p] = As[kk][ty * 4 + p];
            #pragma unroll
            for (int q = 0; q < 4; ++q) bb[q] = Bs[kk][tx * 4 + q];
            #pragma unroll
            for (int p = 0; p < 4; ++p)
                #pragma unroll
                for (int q = 0; q < 4; ++q)
                    c[p][q] = fmaf(a[p], bb[q], c[p][q]);
        }
        __syncthreads();
    }

    #pragma unroll
    for (int p = 0; p < 4; ++p)
        #pragma unroll
        for (int q = 0; q < 4; ++q)
            out[(size_t)(o0 + ty * 4 + p) * TT + t0 + tx * 4 + q] = c[p][q];
}

// ---------------------------------------------------------------------------
extern "C" void kernel_launch(void* const* d_in, const int* in_sizes, int n_in,
                              void* d_out, int out_size) {
    const float* x    = (const float*)d_in[0];   // [4096, 2048]
    const float* Wres = (const float*)d_in[1];   // [4096, 4096]
    const float* wout = (const float*)d_in[2];   // [512, 4096]
    float* out = (float*)d_out;                  // [512, 2048]

    cudaFuncSetAttribute(rc_kernel, cudaFuncAttributeMaxDynamicSharedMemorySize, SMEMB);

    void* flagp = nullptr;
    void* gp    = nullptr;
    cudaGetSymbolAddress(&flagp, d_flag);
    cudaGetSymbolAddress(&gp, d_G);
    // Padding flags (>= NCTA) must always pass the ">= t" test:
    cudaMemsetAsync(flagp, 0xFF, 256 * sizeof(unsigned));
    cudaMemsetAsync(flagp, 0, NCTA * sizeof(unsigned));     // real flags = 0
    cudaMemsetAsync(gp, 0, FEAT * sizeof(__half));          // feats_0 = 0

    convert_kernel<<<1024, 256>>>(Wres);
    rc_kernel<<<NCTA, NTHREADS, SMEMB>>>(x);
    out_gemm<<<dim3(TT / 64, ODIM / 64), 256>>>(wout, out);
}

// round 6
// speedup vs baseline: 2.6826x; 2.1381x over previous
#include <cuda_runtime.h>
#include <cuda_fp16.h>

#define FEAT 4096
#define TT   2048
#define ODIM 512
#define NCTA 148
#define NTHREADS 1024
#define SMEMB (28 * FEAT * 2)   // 28 rows of fp16 weights = 229376 bytes

// Static device scratch (no runtime allocation allowed)
__device__ __half   d_Wh[(size_t)FEAT * FEAT];      // fp16 W_res, 33.5 MB
__device__ __half   d_G[(size_t)(TT + 1) * FEAT];   // feats history (fp16), 16.8 MB
__device__ unsigned d_cnt[TT];                      // per-step arrival counters

// ---------------------------------------------------------------------------
// fp32 -> fp16 weight conversion
// ---------------------------------------------------------------------------
__global__ void convert_kernel(const float* __restrict__ W) {
    size_t n = (size_t)FEAT * FEAT / 4;
    for (size_t i = blockIdx.x * (size_t)blockDim.x + threadIdx.x; i < n;
         i += (size_t)gridDim.x * blockDim.x) {
        float4 v = reinterpret_cast<const float4*>(W)[i];
        __half2 h0 = __floats2half2_rn(v.x, v.y);
        __half2 h1 = __floats2half2_rn(v.z, v.w);
        uint2 u;
        u.x = *reinterpret_cast<unsigned*>(&h0);
        u.y = *reinterpret_cast<unsigned*>(&h1);
        reinterpret_cast<uint2*>(d_Wh)[i] = u;
    }
}

// ---------------------------------------------------------------------------
// Sync primitives (R2-proven: single counter, release-red + acquire-poll)
// ---------------------------------------------------------------------------
__device__ __forceinline__ unsigned ld_acq(const unsigned* p) {
    unsigned v;
    asm volatile("ld.acquire.gpu.global.u32 %0, [%1];" : "=r"(v) : "l"(p) : "memory");
    return v;
}
__device__ __forceinline__ void red_rel_add1(unsigned* p) {
    asm volatile("red.release.gpu.global.add.u32 [%0], 1;" :: "l"(p) : "memory");
}

__device__ __forceinline__ void h8_to_f(uint4 u, float* o) {
    __half2* h = reinterpret_cast<__half2*>(&u);
    float2 a = __half22float2(h[0]);
    float2 b = __half22float2(h[1]);
    float2 c = __half22float2(h[2]);
    float2 d = __half22float2(h[3]);
    o[0] = a.x; o[1] = a.y; o[2] = b.x; o[3] = b.y;
    o[4] = c.x; o[5] = c.y; o[6] = d.x; o[7] = d.y;
}

// ---------------------------------------------------------------------------
// Persistent recurrence kernel: 148 CTAs, each owns <=28 rows of W in SMEM.
// Hot loop: pure HFMA2 (fp16 weights x fp16 feats, fp16 4-product partials,
// fp32 cross-chunk/cross-lane reduction).
// Warp layout: 32 warps = 4 row-groups x 8 k-groups.
//   warp w: rg = w&3 (rows rg*7..rg*7+6), kg = w>>2 (k in [kg*512, kg*512+512))
//   lane l: 2 chunks of 8 contiguous halves at cb = kg*512 + l*8 and cb+256
// ---------------------------------------------------------------------------
extern "C" __global__ void __launch_bounds__(NTHREADS, 1)
rc_kernel(const float* __restrict__ x) {
    extern __shared__ __half sW[];            // [nrows][FEAT]
    __shared__ float sPart[28][9];            // stride 9 -> conflict-free

    const int b   = blockIdx.x;
    const int tid = threadIdx.x;

    // Row distribution: first 100 CTAs get 28 rows, last 48 get 27 (=4096).
    int r0, nrows;
    if (b < 100) { r0 = b * 28;               nrows = 28; }
    else         { r0 = 2800 + (b - 100) * 27; nrows = 27; }

    // Stage W slice into SMEM (once)
    {
        const uint4* wg = reinterpret_cast<const uint4*>(d_Wh + (size_t)r0 * FEAT);
        uint4* ws = reinterpret_cast<uint4*>(sW);
        int nv = nrows * FEAT / 8;            // uint4 = 8 halfs
        for (int i = tid; i < nv; i += NTHREADS) ws[i] = wg[i];
    }
    __syncthreads();

    const int w    = tid >> 5;
    const int lane = tid & 31;
    const int rg   = w & 3;
    const int kg   = w >> 2;
    const int rbeg = rg * 7;
    const int rend = min(rbeg + 7, nrows);
    const int cb   = kg * 512 + lane * 8;

    for (int t = 0; t < TT; ++t) {
        // Prefetch x[:, t] for this CTA's rows (in flight during the poll)
        float xv = 0.f;
        if (tid < nrows) xv = __ldg(&x[(size_t)(r0 + tid) * TT + t]);

        if (t > 0) {
            if (tid == 0) {
                while (ld_acq(&d_cnt[t - 1]) < NCTA) { }
            }
            __syncthreads();
        }

        // Load this lane's 16 features as 8 x half2 (no conversion)
        const __half* f = d_G + (size_t)t * FEAT;
        uint4 fa = __ldcg(reinterpret_cast<const uint4*>(f + cb));
        uint4 fb = __ldcg(reinterpret_cast<const uint4*>(f + cb + 256));
        __half2 fh[8];
        {
            __half2* pa = reinterpret_cast<__half2*>(&fa);
            __half2* pb = reinterpret_cast<__half2*>(&fb);
            fh[0] = pa[0]; fh[1] = pa[1]; fh[2] = pa[2]; fh[3] = pa[3];
            fh[4] = pb[0]; fh[5] = pb[1]; fh[6] = pb[2]; fh[7] = pb[3];
        }

        float acc[7];
        #pragma unroll
        for (int j = 0; j < 7; ++j) acc[j] = 0.f;

        #pragma unroll
        for (int j = 0; j < 7; ++j) {
            int r = rbeg + j;
            if (r < rend) {
                const __half* wr = sW + (size_t)r * FEAT + cb;
                uint4 wa = *reinterpret_cast<const uint4*>(wr);
                uint4 wb = *reinterpret_cast<const uint4*>(wr + 256);
                __half2* wha = reinterpret_cast<__half2*>(&wa);
                __half2* whb = reinterpret_cast<__half2*>(&wb);
                // Two 4-deep fp16 accumulation chains (4 products each lane)
                __half2 a0 = __hmul2(wha[0], fh[0]);
                __half2 a1 = __hmul2(wha[1], fh[1]);
                a0 = __hfma2(wha[2], fh[2], a0);
                a1 = __hfma2(wha[3], fh[3], a1);
                a0 = __hfma2(whb[0], fh[4], a0);
                a1 = __hfma2(whb[1], fh[5], a1);
                a0 = __hfma2(whb[2], fh[6], a0);
                a1 = __hfma2(whb[3], fh[7], a1);
                __half2 s2 = __hadd2(a0, a1);
                acc[j] = __low2float(s2) + __high2float(s2);
            }
        }

        // Warp reduction over 32 lanes for each of this warp's rows (fp32)
        #pragma unroll
        for (int j = 0; j < 7; ++j) {
            float v = acc[j];
            v += __shfl_down_sync(0xFFFFFFFFu, v, 16);
            v += __shfl_down_sync(0xFFFFFFFFu, v, 8);
            v += __shfl_down_sync(0xFFFFFFFFu, v, 4);
            v += __shfl_down_sync(0xFFFFFFFFu, v, 2);
            v += __shfl_down_sync(0xFFFFFFFFu, v, 1);
            if (lane == 0 && rbeg + j < rend) sPart[rbeg + j][kg] = v;
        }
        __syncthreads();

        // Threads 0..nrows-1 (warp 0): sum partials, clamp, store, release.
        if (tid < nrows) {
            float s = 0.f;
            #pragma unroll
            for (int k = 0; k < 8; ++k) s += sPart[tid][k];
            s += xv;
            s = fminf(fmaxf(s, -1.f), 1.f);
            d_G[(size_t)(t + 1) * FEAT + r0 + tid] = __float2half_rn(s);
        }
        __syncthreads();                       // orders stores before release
        if (tid == 0) red_rel_add1(&d_cnt[t]); // cumulative release
    }
}

// ---------------------------------------------------------------------------
// Readout GEMM: out[o][t] = sum_f w_out[o][f] * G[t+1][f]   (G is fp16)
// 64x64 tile per block, BK=32, 256 threads, 4x4 micro-tile per thread.
// ---------------------------------------------------------------------------
__global__ void __launch_bounds__(256)
out_gemm(const float* __restrict__ wout, float* __restrict__ out) {
    __shared__ float As[32][65];   // As[k][i]  (i: out rows)
    __shared__ float Bs[32][65];   // Bs[k][j]  (j: timesteps)

    const int t0 = blockIdx.x * 64;
    const int o0 = blockIdx.y * 64;
    const int tid = threadIdx.x;
    const int tx = tid & 15, ty = tid >> 4;

    float c[4][4];
    #pragma unroll
    for (int p = 0; p < 4; ++p)
        #pragma unroll
        for (int q = 0; q < 4; ++q) c[p][q] = 0.f;

    for (int k0 = 0; k0 < FEAT; k0 += 32) {
        #pragma unroll
        for (int it = 0; it < 2; ++it) {
            int idx = it * 256 + tid;          // 0..511
            int i  = idx >> 3;                 // 0..63
            int kv = (idx & 7) * 4;            // 0,4,..28
            float4 v = *reinterpret_cast<const float4*>(
                &wout[(size_t)(o0 + i) * FEAT + k0 + kv]);
            As[kv + 0][i] = v.x; As[kv + 1][i] = v.y;
            As[kv + 2][i] = v.z; As[kv + 3][i] = v.w;
        }
        {
            int j  = tid >> 2;                 // 0..63
            int kv = (tid & 3) * 8;            // 0,8,16,24
            uint4 u = *reinterpret_cast<const uint4*>(
                &d_G[(size_t)(t0 + j + 1) * FEAT + k0 + kv]);
            float bf[8];
            h8_to_f(u, bf);
            #pragma unroll
            for (int q = 0; q < 8; ++q) Bs[kv + q][j] = bf[q];
        }
        __syncthreads();

        #pragma unroll
        for (int kk = 0; kk < 32; ++kk) {
            float a[4], bb[4];
            #pragma unroll
            for (int p = 0; p < 4; ++p) a[p] = As[kk][ty * 4 + p];
            #pragma unroll
            for (int q = 0; q < 4; ++q) bb[q] = Bs[kk][tx * 4 + q];
            #pragma unroll
            for (int p = 0; p < 4; ++p)
                #pragma unroll
                for (int q = 0; q < 4; ++q)
                    c[p][q] = fmaf(a[p], bb[q], c[p][q]);
        }
        __syncthreads();
    }

    #pragma unroll
    for (int p = 0; p < 4; ++p)
        #pragma unroll
        for (int q = 0; q < 4; ++q)
            out[(size_t)(o0 + ty * 4 + p) * TT + t0 + tx * 4 + q] = c[p][q];
}

// ---------------------------------------------------------------------------
extern "C" void kernel_launch(void* const* d_in, const int* in_sizes, int n_in,
                              void* d_out, int out_size) {
    const float* x    = (const float*)d_in[0];   // [4096, 2048]
    const float* Wres = (const float*)d_in[1];   // [4096, 4096]
    const float* wout = (const float*)d_in[2];   // [512, 4096]
    float* out = (float*)d_out;                  // [512, 2048]

    cudaFuncSetAttribute(rc_kernel, cudaFuncAttributeMaxDynamicSharedMemorySize, SMEMB);

    void* cntp = nullptr;
    void* gp   = nullptr;
    cudaGetSymbolAddress(&cntp, d_cnt);
    cudaGetSymbolAddress(&gp, d_G);
    cudaMemsetAsync(cntp, 0, TT * sizeof(unsigned));     // reset step counters
    cudaMemsetAsync(gp, 0, FEAT * sizeof(__half));       // feats_0 = 0 (fp16)

    convert_kernel<<<1024, 256>>>(Wres);
    rc_kernel<<<NCTA, NTHREADS, SMEMB>>>(x);
    out_gemm<<<dim3(TT / 64, ODIM / 64), 256>>>(wout, out);
}